// round 11
// baseline (speedup 1.0000x reference)
#include <cuda_runtime.h>
#include <cuda_fp16.h>
#include <cstdint>

// Problem constants
#define Bsz 2
#define Sq  2048
#define HIDN 512
#define NHh 8
#define Dh  64
#define GH  (Bsz*NHh)

// ---------------------------------------------------------------------------
// Scratch (__device__ globals; allocation-free rule)
// ---------------------------------------------------------------------------
__device__ __align__(128) __half g_q16 [Bsz*Sq*HIDN];   // fp16 inputs
__device__ __align__(128) __half g_k16 [Bsz*Sq*HIDN];
__device__ __align__(128) __half g_v16h[Bsz*Sq*HIDN];   // v split
__device__ __align__(128) __half g_v16l[Bsz*Sq*HIDN];
__device__ __align__(128) __half g_Wq16[HIDN*HIDN];
__device__ __align__(128) __half g_Wk16[HIDN*HIDN];
__device__ __align__(128) __half g_Wvh [HIDN*HIDN];     // Wv split
__device__ __align__(128) __half g_Wvl [HIDN*HIDN];
__device__ __align__(128) __half g_Woh [HIDN*HIDN];     // Wo split
__device__ __align__(128) __half g_Wol [HIDN*HIDN];

__device__ __align__(128) __half g_qh [GH*Sq*Dh];       // [g][s][d] scaled
__device__ __align__(128) __half g_kh [GH*Sq*Dh];       // [g][s][d]
__device__ __align__(128) __half g_vh [GH*Dh*Sq];       // [g][d][s] split
__device__ __align__(128) __half g_vl [GH*Dh*Sq];
__device__ __align__(128) __half g_xh [(long)GH*Sq*Sq]; // scores fp16
__device__ __align__(128) __half g_wTh[(long)Bsz*Sq*Sq];// w^T fp16
__device__ __align__(128) float  g_y  [(long)GH*Sq*Sq]; // logits fp32
__device__ __align__(128) __half g_ph [(long)GH*Sq*Sq]; // softmax split
__device__ __align__(128) __half g_pl [(long)GH*Sq*Sq];
__device__ __align__(128) __half g_oh [Bsz*Sq*HIDN];    // o split [b][s][hd]
__device__ __align__(128) __half g_ol [Bsz*Sq*HIDN];
__device__ int g_mask_mode;

// ---------------------------------------------------------------------------
// Mask dtype sniffer
// ---------------------------------------------------------------------------
__global__ void detect_mask_kernel(const unsigned int* __restrict__ m, int nwords) {
    __shared__ int s_multi;
    if (threadIdx.x == 0) s_multi = 0;
    __syncthreads();
    int found = 0;
    for (int i = threadIdx.x; i < nwords; i += blockDim.x) {
        unsigned int v = m[i];
        if (v > 1u && v != 0x3F800000u) found = 1;
    }
    if (found) atomicOr(&s_multi, 1);
    __syncthreads();
    if (threadIdx.x == 0) g_mask_mode = s_multi ? 2 : 0;
}
__device__ __forceinline__ bool mask_true(const void* mask, long idx) {
    if (g_mask_mode == 2) return ((const unsigned char*)mask)[idx] != 0;
    return ((const unsigned int*)mask)[idx] != 0u;
}

// ---------------------------------------------------------------------------
// Conversions (vectorized: float4 in, half2 out)
// ---------------------------------------------------------------------------
enum { C_Q = 0, C_K, C_WQ, C_WK };
enum { S_V = 0, S_WV, S_WO };

template <int WHICH>
__global__ void conv_half_t(const float* __restrict__ s, int n) {
    __half* d = (WHICH == C_Q)  ? g_q16 :
                (WHICH == C_K)  ? g_k16 :
                (WHICH == C_WQ) ? g_Wq16 : g_Wk16;
    int i = (blockIdx.x * blockDim.x + threadIdx.x) * 4;
    if (i < n) {
        float4 v = *(const float4*)(s + i);
        ((__half2*)(d + i))[0] = __floats2half2_rn(v.x, v.y);
        ((__half2*)(d + i))[1] = __floats2half2_rn(v.z, v.w);
    }
}

template <int WHICH>
__global__ void conv_split_t(const float* __restrict__ s, int n) {
    __half* h = (WHICH == S_V) ? g_v16h : (WHICH == S_WV) ? g_Wvh : g_Woh;
    __half* l = (WHICH == S_V) ? g_v16l : (WHICH == S_WV) ? g_Wvl : g_Wol;
    int i = (blockIdx.x * blockDim.x + threadIdx.x) * 4;
    if (i < n) {
        float4 v = *(const float4*)(s + i);
        float f[4] = {v.x, v.y, v.z, v.w};
        __half hh[4], ll[4];
        #pragma unroll
        for (int j = 0; j < 4; j++) {
            hh[j] = __float2half(f[j]);
            ll[j] = __float2half(f[j] - __half2float(hh[j]));
        }
        *(uint2*)(h + i) = *(uint2*)hh;
        *(uint2*)(l + i) = *(uint2*)ll;
    }
}

// w transpose -> fp16
__global__ void transpose_w_kernel(const float* __restrict__ w) {
    __shared__ float t[32][33];
    int b = blockIdx.z;
    int k0 = blockIdx.y * 32, l0 = blockIdx.x * 32;
    const float* wb = w + (long)b * Sq * Sq;
    __half* ob = g_wTh + (long)b * Sq * Sq;
    int x = threadIdx.x, y = threadIdx.y;
    #pragma unroll
    for (int i = 0; i < 32; i += 8)
        t[y + i][x] = wb[(long)(k0 + y + i) * Sq + (l0 + x)];
    __syncthreads();
    #pragma unroll
    for (int i = 0; i < 32; i += 8)
        ob[(long)(l0 + y + i) * Sq + (k0 + x)] = __float2half(t[x][y + i]);
}

// ---------------------------------------------------------------------------
// HMMA primitives
// ---------------------------------------------------------------------------
static __device__ __forceinline__ uint32_t sw64 (uint32_t x) { return x ^ ((x >> 3) & 0x30); }
static __device__ __forceinline__ uint32_t sw128(uint32_t x) { return x ^ ((x >> 3) & 0x70); }

__device__ __forceinline__ void cp_async16(uint32_t saddr, const void* gaddr) {
    asm volatile("cp.async.cg.shared.global [%0], [%1], 16;"
                 :: "r"(saddr), "l"(gaddr) : "memory");
}
__device__ __forceinline__ void ldsm_x4(uint32_t* r, uint32_t addr) {
    asm volatile("ldmatrix.sync.aligned.m8n8.x4.shared.b16 {%0,%1,%2,%3}, [%4];"
                 : "=r"(r[0]), "=r"(r[1]), "=r"(r[2]), "=r"(r[3]) : "r"(addr));
}
__device__ __forceinline__ void mma16816(float* c, const uint32_t* a, const uint32_t* b) {
    asm volatile(
        "mma.sync.aligned.m16n8k16.row.col.f32.f16.f16.f32 "
        "{%0,%1,%2,%3}, {%4,%5,%6,%7}, {%8,%9}, {%0,%1,%2,%3};"
        : "+f"(c[0]), "+f"(c[1]), "+f"(c[2]), "+f"(c[3])
        : "r"(a[0]), "r"(a[1]), "r"(a[2]), "r"(a[3]), "r"(b[0]), "r"(b[1]));
}

// ===========================================================================
// XW v3: y = x @ w^T per head.  256 threads (8 warps, 4x2), BM=256, BN=128,
// k-tile 64 (128B SW128 rows), 3-stage dynamic smem, reg double-buffered.
// ===========================================================================
#define X3STAGE 49152                    // (256+128) rows * 128B
#define X3SMEM  (3*X3STAGE)              // 144 KB dynamic

__global__ void __launch_bounds__(256) xw3_kernel() {
    extern __shared__ __align__(1024) char smem3[];
    uint32_t sbase = (uint32_t)__cvta_generic_to_shared(smem3);

    int tid = threadIdx.x;
    int wid = tid >> 5, lane = tid & 31;
    int wm = (wid >> 1) * 64;        // 4 m-blocks
    int wn = (wid & 1) * 64;         // 2 n-blocks

    int g  = blockIdx.z;
    int m0 = blockIdx.y * 256;
    int n0 = blockIdx.x * 128;
    const __half* Ag = g_xh  + (long)g        * Sq * Sq + (long)m0 * Sq;
    const __half* Bg = g_wTh + (long)(g >> 3) * Sq * Sq + (long)n0 * Sq;

    float c[4][8][4];
    #pragma unroll
    for (int t = 0; t < 4; t++)
        #pragma unroll
        for (int u = 0; u < 8; u++)
            #pragma unroll
            for (int i = 0; i < 4; i++) c[t][u][i] = 0.f;

    // stage: A rows 0-255, B rows 256-383, each 128B, SW128
    auto load_stage = [&](int st, int kt) {
        uint32_t base = sbase + st * X3STAGE;
        const __half* Ak = Ag + kt * 64;
        const __half* Bk = Bg + kt * 64;
        #pragma unroll
        for (int it = 0; it < 12; it++) {
            int t = tid + it * 256;            // 0..3071
            int r = t >> 3, ch = t & 7;
            if (r < 256)
                cp_async16(base + sw128(r * 128 + ch * 16),
                           Ak + (long)r * Sq + ch * 8);
            else {
                int rb = r - 256;
                cp_async16(base + 32768 + sw128(rb * 128 + ch * 16),
                           Bk + (long)rb * Sq + ch * 8);
            }
        }
    };

    load_stage(0, 0);
    asm volatile("cp.async.commit_group;" ::: "memory");
    load_stage(1, 1);
    asm volatile("cp.async.commit_group;" ::: "memory");

    uint32_t a[2][4][4], b[2][8][2];

    for (int kt = 0; kt < 32; kt++) {       // K=2048, tile 64
        int st = kt % 3;
        asm volatile("cp.async.wait_group 1;" ::: "memory");
        __syncthreads();

        int kn = kt + 2;
        if (kn < 32) load_stage(kn % 3, kn);
        asm volatile("cp.async.commit_group;" ::: "memory");

        uint32_t abase = sbase + st * X3STAGE;
        uint32_t bbase = abase + 32768;

        auto load_a = [&](int buf, int ks) {
            #pragma unroll
            for (int t = 0; t < 4; t++) {
                int row = wm + t * 16 + (lane & 15);
                ldsm_x4(a[buf][t], abase + sw128(row * 128 + ks * 32 + (lane >> 4) * 16));
            }
        };
        auto load_b = [&](int buf, int ks) {
            #pragma unroll
            for (int u = 0; u < 8; u += 2) {
                int grp = lane >> 3;
                int row = wn + u * 8 + (grp >> 1) * 8 + (lane & 7);
                int kb  = (grp & 1) * 16;
                uint32_t rr[4];
                ldsm_x4(rr, bbase + sw128(row * 128 + ks * 32 + kb));
                b[buf][u][0] = rr[0];     b[buf][u][1] = rr[1];
                b[buf][u + 1][0] = rr[2]; b[buf][u + 1][1] = rr[3];
            }
        };

        load_a(0, 0);
        load_b(0, 0);
        #pragma unroll
        for (int ks = 0; ks < 4; ks++) {
            int cur = ks & 1, nxt = cur ^ 1;
            if (ks < 3) { load_a(nxt, ks + 1); load_b(nxt, ks + 1); }
            #pragma unroll
            for (int t = 0; t < 4; t++)
                #pragma unroll
                for (int u = 0; u < 8; u++)
                    mma16816(c[t][u], a[cur][t], b[cur][u]);
        }
    }

    // epilogue -> g_y fp32
    float* Cg = g_y + (long)g * Sq * Sq;
    #pragma unroll
    for (int t = 0; t < 4; t++) {
        int m = m0 + wm + t * 16 + (lane >> 2);
        #pragma unroll
        for (int u = 0; u < 8; u++) {
            int n = n0 + wn + u * 8 + (lane & 3) * 2;
            float* p = Cg + (long)m * Sq + n;
            p[0] = c[t][u][0]; p[1] = c[t][u][1];
            p[8 * Sq] = c[t][u][2]; p[8 * Sq + 1] = c[t][u][3];
        }
    }
}

// ===========================================================================
// OGEMM v2: o = p @ v^T per head (3-segment split-fp16).  128 threads (2x2),
// BM=128, BN=64, k-tile 64, 3-stage dynamic smem, reg double-buffered.
// ===========================================================================
#define OSTAGE 24576                     // (128+64) rows * 128B
#define OSMEM  (3*OSTAGE)                // 72 KB dynamic

__global__ void __launch_bounds__(128) og2_kernel() {
    extern __shared__ __align__(1024) char smemo[];
    uint32_t sbase = (uint32_t)__cvta_generic_to_shared(smemo);

    int tid = threadIdx.x;
    int wid = tid >> 5, lane = tid & 31;
    int wm = (wid >> 1) * 64;
    int wn = (wid & 1) * 32;

    int g  = blockIdx.z;
    int m0 = blockIdx.y * 128;
    long ao = (long)g * Sq * Sq + (long)m0 * Sq;
    long bo = (long)g * Dh * Sq;
    const __half* Aseg[3] = { g_ph + ao, g_ph + ao, g_pl + ao };
    const __half* Bseg[3] = { g_vh + bo, g_vl + bo, g_vh + bo };

    float c[4][4][4];
    #pragma unroll
    for (int t = 0; t < 4; t++)
        #pragma unroll
        for (int u = 0; u < 4; u++)
            #pragma unroll
            for (int i = 0; i < 4; i++) c[t][u][i] = 0.f;

    auto load_stage = [&](int st, int kt) {
        int seg = kt >> 5, kk = kt & 31;     // 32 k-tiles per segment
        const __half* Ak = Aseg[seg] + kk * 64;
        const __half* Bk = Bseg[seg] + kk * 64;
        uint32_t base = sbase + st * OSTAGE;
        #pragma unroll
        for (int it = 0; it < 12; it++) {
            int t = tid + it * 128;            // 0..1535
            int r = t >> 3, ch = t & 7;
            if (r < 128)
                cp_async16(base + sw128(r * 128 + ch * 16),
                           Ak + (long)r * Sq + ch * 8);
            else {
                int rb = r - 128;
                cp_async16(base + 16384 + sw128(rb * 128 + ch * 16),
                           Bk + (long)rb * Sq + ch * 8);
            }
        }
    };

    load_stage(0, 0);
    asm volatile("cp.async.commit_group;" ::: "memory");
    load_stage(1, 1);
    asm volatile("cp.async.commit_group;" ::: "memory");

    uint32_t a[2][4][4], b[2][4][2];

    for (int kt = 0; kt < 96; kt++) {        // 3 segs x 32 tiles
        int st = kt % 3;
        asm volatile("cp.async.wait_group 1;" ::: "memory");
        __syncthreads();

        int kn = kt + 2;
        if (kn < 96) load_stage(kn % 3, kn);
        asm volatile("cp.async.commit_group;" ::: "memory");

        uint32_t abase = sbase + st * OSTAGE;
        uint32_t bbase = abase + 16384;

        auto load_a = [&](int buf, int ks) {
            #pragma unroll
            for (int t = 0; t < 4; t++) {
                int row = wm + t * 16 + (lane & 15);
                ldsm_x4(a[buf][t], abase + sw128(row * 128 + ks * 32 + (lane >> 4) * 16));
            }
        };
        auto load_b = [&](int buf, int ks) {
            #pragma unroll
            for (int u = 0; u < 4; u += 2) {
                int grp = lane >> 3;
                int row = wn + u * 8 + (grp >> 1) * 8 + (lane & 7);
                int kb  = (grp & 1) * 16;
                uint32_t rr[4];
                ldsm_x4(rr, bbase + sw128(row * 128 + ks * 32 + kb));
                b[buf][u][0] = rr[0];     b[buf][u][1] = rr[1];
                b[buf][u + 1][0] = rr[2]; b[buf][u + 1][1] = rr[3];
            }
        };

        load_a(0, 0);
        load_b(0, 0);
        #pragma unroll
        for (int ks = 0; ks < 4; ks++) {
            int cur = ks & 1, nxt = cur ^ 1;
            if (ks < 3) { load_a(nxt, ks + 1); load_b(nxt, ks + 1); }
            #pragma unroll
            for (int t = 0; t < 4; t++)
                #pragma unroll
                for (int u = 0; u < 4; u++)
                    mma16816(c[t][u], a[cur][t], b[cur][u]);
        }
    }

    // epilogue: split write to g_oh/g_ol
    int b_ = g >> 3, h = g & 7;
    #pragma unroll
    for (int t = 0; t < 4; t++) {
        int m = m0 + wm + t * 16 + (lane >> 2);
        #pragma unroll
        for (int u = 0; u < 4; u++) {
            int n = wn + u * 8 + (lane & 3) * 2;
            #pragma unroll
            for (int half_ = 0; half_ < 2; half_++) {
                int mm = m + half_ * 8;
                float v0 = c[t][u][half_ * 2], v1 = c[t][u][half_ * 2 + 1];
                long idx = ((long)(b_ * Sq + mm)) * HIDN + h * Dh + n;
                __half h0 = __float2half(v0), h1 = __float2half(v1);
                g_oh[idx]     = h0;
                g_oh[idx + 1] = h1;
                g_ol[idx]     = __float2half(v0 - __half2float(h0));
                g_ol[idx + 1] = __float2half(v1 - __half2float(h1));
            }
        }
    }
}

// ---------------------------------------------------------------------------
// Unified HMMA GEMM template (proj/scores/out).  NT: C = sum_seg A B^T.
// 128 threads, 2x2 warps.  3-stage cp.async, SW64, k-tile 32.
// ---------------------------------------------------------------------------
enum { M_QPROJ = 0, M_KPROJ, M_VPROJ, M_SCORES, M_OUT };

template <int BM, int BN, int MODE>
__global__ void __launch_bounds__(128)
hgemm(const float* __restrict__ bias, const float* __restrict__ attn_bias,
      const void* __restrict__ mask, float* __restrict__ Cext)
{
    constexpr int KD   = (MODE == M_SCORES) ? 64 : 512;
    constexpr int NSEG = (MODE == M_VPROJ || MODE == M_OUT) ? 3 : 1;
    constexpr int TPS  = KD / 32;
    constexpr int TOT  = NSEG * TPS;
    constexpr int ROWS = BM + BN;
    constexpr int STAGE = ROWS * 64;
    constexpr int TMF = BM / 2 / 16;
    constexpr int TNF = BN / 2 / 8;

    __shared__ __align__(1024) char smem[3 * STAGE];
    uint32_t sbase = (uint32_t)__cvta_generic_to_shared(smem);

    int tid = threadIdx.x;
    int wid = tid >> 5, lane = tid & 31;
    int wm = (wid >> 1) * (BM / 2);
    int wn = (wid & 1) * (BN / 2);

    int g  = blockIdx.z;
    int m0 = blockIdx.y * BM;
    int n0 = blockIdx.x * BN;

    const __half *A0, *A1 = nullptr, *A2 = nullptr;
    const __half *B0, *B1 = nullptr, *B2 = nullptr;
    if (MODE == M_QPROJ)      { A0 = g_q16;  B0 = g_Wq16; }
    else if (MODE == M_KPROJ) { A0 = g_k16;  B0 = g_Wk16; }
    else if (MODE == M_VPROJ) { A0 = g_v16h; A1 = g_v16h; A2 = g_v16l;
                                B0 = g_Wvh;  B1 = g_Wvl;  B2 = g_Wvh; }
    else if (MODE == M_SCORES){ A0 = g_qh + (long)g * Sq * Dh;
                                B0 = g_kh + (long)g * Sq * Dh; }
    else                      { A0 = g_oh;  A1 = g_oh; A2 = g_ol;
                                B0 = g_Woh; B1 = g_Wol; B2 = g_Woh; }
    A0 += (long)m0 * KD; if (NSEG == 3) { A1 += (long)m0 * KD; A2 += (long)m0 * KD; }
    B0 += (long)n0 * KD; if (NSEG == 3) { B1 += (long)n0 * KD; B2 += (long)n0 * KD; }

    float c[TMF][TNF][4];
    #pragma unroll
    for (int t = 0; t < TMF; t++)
        #pragma unroll
        for (int u = 0; u < TNF; u++)
            #pragma unroll
            for (int i = 0; i < 4; i++) c[t][u][i] = 0.f;

    auto load_stage = [&](int st, int kt) {
        int seg = kt / TPS, kk = kt % TPS;
        const __half* Ak = (NSEG == 1 || seg == 0) ? A0 : (seg == 1) ? A1 : A2;
        const __half* Bk = (NSEG == 1 || seg == 0) ? B0 : (seg == 1) ? B1 : B2;
        Ak += kk * 32; Bk += kk * 32;
        uint32_t base = sbase + st * STAGE;
        #pragma unroll
        for (int t = tid; t < ROWS * 4; t += 128) {
            int r = t >> 2, ch = t & 3;
            if (r < BM)
                cp_async16(base + sw64(r * 64 + ch * 16),
                           Ak + (long)r * KD + ch * 8);
            else {
                int rb = r - BM;
                cp_async16(base + BM * 64 + sw64(rb * 64 + ch * 16),
                           Bk + (long)rb * KD + ch * 8);
            }
        }
    };

    load_stage(0, 0);
    asm volatile("cp.async.commit_group;" ::: "memory");
    if (TOT > 1) load_stage(1, 1);
    asm volatile("cp.async.commit_group;" ::: "memory");

    for (int kt = 0; kt < TOT; kt++) {
        int st = kt % 3;
        asm volatile("cp.async.wait_group 1;" ::: "memory");
        __syncthreads();

        int kn = kt + 2;
        if (kn < TOT) load_stage(kn % 3, kn);
        asm volatile("cp.async.commit_group;" ::: "memory");

        uint32_t abase = sbase + st * STAGE;
        uint32_t bbase = abase + BM * 64;
        #pragma unroll
        for (int ks = 0; ks < 2; ks++) {
            uint32_t a[TMF][4], b[TNF][2];
            #pragma unroll
            for (int t = 0; t < TMF; t++) {
                int row = wm + t * 16 + (lane & 15);
                ldsm_x4(a[t], abase + sw64(row * 64 + ks * 32 + (lane >> 4) * 16));
            }
            #pragma unroll
            for (int u = 0; u < TNF; u += 2) {
                int grp = lane >> 3;
                int row = wn + u * 8 + (grp >> 1) * 8 + (lane & 7);
                int kb  = (grp & 1) * 16;
                uint32_t rr[4];
                ldsm_x4(rr, bbase + sw64(row * 64 + ks * 32 + kb));
                b[u][0] = rr[0]; b[u][1] = rr[1];
                b[u + 1][0] = rr[2]; b[u + 1][1] = rr[3];
            }
            #pragma unroll
            for (int t = 0; t < TMF; t++)
                #pragma unroll
                for (int u = 0; u < TNF; u++)
                    mma16816(c[t][u], a[t], b[u]);
        }
    }

    auto store = [&](int m, int n, float v) {
        if (MODE == M_QPROJ) {
            float val = (v + bias[n]) * 0.125f;
            int b_ = m >> 11, s = m & 2047, h = n >> 6, d = n & 63;
            g_qh[((long)((b_ * NHh + h) * Sq + s)) * Dh + d] = __float2half(val);
        } else if (MODE == M_KPROJ) {
            float val = v + bias[n];
            int b_ = m >> 11, s = m & 2047, h = n >> 6, d = n & 63;
            g_kh[((long)((b_ * NHh + h) * Sq + s)) * Dh + d] = __float2half(val);
        } else if (MODE == M_VPROJ) {
            float val = v + bias[n];
            int b_ = m >> 11, s = m & 2047, h = n >> 6, d = n & 63;
            long idx = ((long)((b_ * NHh + h) * Dh + d)) * Sq + s;
            __half hh = __float2half(val);
            g_vh[idx] = hh;
            g_vl[idx] = __float2half(val - __half2float(hh));
        } else if (MODE == M_SCORES) {
            long idx  = (long)g * Sq * Sq + (long)m * Sq + n;
            long midx = (long)(g >> 3) * Sq * Sq + (long)m * Sq + n;
            float val = v + attn_bias[idx];
            if (mask_true(mask, midx)) val = 0.f;
            g_xh[idx] = __float2half(val);
        } else {  // M_OUT
            Cext[(long)m * HIDN + n] = v + bias[n];
        }
    };

    #pragma unroll
    for (int t = 0; t < TMF; t++) {
        int m = m0 + wm + t * 16 + (lane >> 2);
        #pragma unroll
        for (int u = 0; u < TNF; u++) {
            int n = n0 + wn + u * 8 + (lane & 3) * 2;
            store(m,     n,     c[t][u][0]);
            store(m,     n + 1, c[t][u][1]);
            store(m + 8, n,     c[t][u][2]);
            store(m + 8, n + 1, c[t][u][3]);
        }
    }
}

// ---------------------------------------------------------------------------
// Fused single-read softmax: g_y row (fp32) -> (ph, pl) fp16 split
// ---------------------------------------------------------------------------
__global__ void __launch_bounds__(256) softmax_kernel() {
    long row = blockIdx.x;
    const float* p = g_y + row * Sq;
    __half* oh = g_ph + row * Sq;
    __half* ol = g_pl + row * Sq;
    __shared__ float buf[Sq];
    __shared__ float red[256];
    int t = threadIdx.x;

    float mx = -3.0e38f;
    #pragma unroll
    for (int i = 0; i < Sq / 1024; i++) {
        float4 v = ((const float4*)p)[t + i * 256];
        ((float4*)buf)[t + i * 256] = v;
        mx = fmaxf(mx, fmaxf(fmaxf(v.x, v.y), fmaxf(v.z, v.w)));
    }
    red[t] = mx; __syncthreads();
    for (int s = 128; s > 0; s >>= 1) {
        if (t < s) red[t] = fmaxf(red[t], red[t + s]);
        __syncthreads();
    }
    mx = red[0];
    __syncthreads();

    float sum = 0.f;
    #pragma unroll
    for (int i = 0; i < Sq / 256; i++) {
        float e = expf(buf[t + i * 256] - mx);
        buf[t + i * 256] = e;
        sum += e;
    }
    red[t] = sum; __syncthreads();
    for (int s = 128; s > 0; s >>= 1) {
        if (t < s) red[t] += red[t + s];
        __syncthreads();
    }
    float inv = 1.f / red[0];
    __syncthreads();

    #pragma unroll
    for (int i = 0; i < Sq / 256; i++) {
        float pv = buf[t + i * 256] * inv;
        __half hh = __float2half(pv);
        oh[t + i * 256] = hh;
        ol[t + i * 256] = __float2half(pv - __half2float(hh));
    }
}

// ---------------------------------------------------------------------------
extern "C" void kernel_launch(void* const* d_in, const int* in_sizes, int n_in,
                              void* d_out, int out_size)
{
    const float* q    = (const float*)d_in[0];
    const float* k    = (const float*)d_in[1];
    const float* v    = (const float*)d_in[2];
    const float* ab   = (const float*)d_in[3];
    const void*  mask = d_in[4];
    const float* w    = (const float*)d_in[5];
    const float* Wq   = (const float*)d_in[6];
    const float* bq   = (const float*)d_in[7];
    const float* Wk   = (const float*)d_in[8];
    const float* bk   = (const float*)d_in[9];
    const float* Wv   = (const float*)d_in[10];
    const float* bv   = (const float*)d_in[11];
    const float* Wo   = (const float*)d_in[12];
    const float* bo   = (const float*)d_in[13];
    float* out = (float*)d_out;

    const int NIN = Bsz * Sq * HIDN;      // 2M
    const int NW  = HIDN * HIDN;          // 256K

    cudaFuncSetAttribute(xw3_kernel,
                         cudaFuncAttributeMaxDynamicSharedMemorySize, X3SMEM);
    cudaFuncSetAttribute(og2_kernel,
                         cudaFuncAttributeMaxDynamicSharedMemorySize, OSMEM);

    detect_mask_kernel<<<1, 256>>>((const unsigned int*)mask, 65536);

    conv_half_t<C_Q> <<<NIN / 4 / 512, 512>>>(q, NIN);
    conv_half_t<C_K> <<<NIN / 4 / 512, 512>>>(k, NIN);
    conv_split_t<S_V><<<NIN / 4 / 512, 512>>>(v, NIN);
    conv_half_t<C_WQ><<<NW / 4 / 128, 128>>>(Wq, NW);
    conv_half_t<C_WK><<<NW / 4 / 128, 128>>>(Wk, NW);
    conv_split_t<S_WV><<<NW / 4 / 128, 128>>>(Wv, NW);
    conv_split_t<S_WO><<<NW / 4 / 128, 128>>>(Wo, NW);

    transpose_w_kernel<<<dim3(64, 64, Bsz), dim3(32, 8)>>>(w);

    // Projections: [4096,512] @ [512,512]^T
    hgemm<128, 128, M_QPROJ><<<dim3(4, 32, 1), 128>>>(bq, nullptr, nullptr, nullptr);
    hgemm<128, 128, M_KPROJ><<<dim3(4, 32, 1), 128>>>(bk, nullptr, nullptr, nullptr);
    hgemm<128, 128, M_VPROJ><<<dim3(4, 32, 1), 128>>>(bv, nullptr, nullptr, nullptr);

    // Scores: [2048,64]@[2048,64]^T + bias, mask -> g_xh
    hgemm<128, 128, M_SCORES><<<dim3(16, 16, GH), 128>>>(nullptr, ab, mask, nullptr);

    // y = x @ w (dominant) — XW v3 (256x128 tiles)
    xw3_kernel<<<dim3(16, 8, GH), 256, X3SMEM>>>();

    softmax_kernel<<<GH * Sq, 256>>>();

    // o = p @ v^T — OGEMM v2 (k-tile 64, reg double-buffered)
    og2_kernel<<<dim3(1, 16, GH), 128, OSMEM>>>();

    // out = o @ Wo^T + bo (split 3-pass)
    hgemm<128, 128, M_OUT><<<dim3(4, 32, 1), 128>>>(bo, nullptr, nullptr, out);
}

// round 12
// speedup vs baseline: 1.0536x; 1.0536x over previous
#include <cuda_runtime.h>
#include <cuda_fp16.h>
#include <cstdint>

// Problem constants
#define Bsz 2
#define Sq  2048
#define HIDN 512
#define NHh 8
#define Dh  64
#define GH  (Bsz*NHh)

// ---------------------------------------------------------------------------
// Scratch (__device__ globals; allocation-free rule)
// ---------------------------------------------------------------------------
__device__ __align__(128) __half g_q16 [Bsz*Sq*HIDN];   // fp16 inputs
__device__ __align__(128) __half g_k16 [Bsz*Sq*HIDN];
__device__ __align__(128) __half g_v16h[Bsz*Sq*HIDN];   // v split
__device__ __align__(128) __half g_v16l[Bsz*Sq*HIDN];
__device__ __align__(128) __half g_Wq16[HIDN*HIDN];
__device__ __align__(128) __half g_Wk16[HIDN*HIDN];
__device__ __align__(128) __half g_Wvh [HIDN*HIDN];     // Wv split
__device__ __align__(128) __half g_Wvl [HIDN*HIDN];
__device__ __align__(128) __half g_Woh [HIDN*HIDN];     // Wo split
__device__ __align__(128) __half g_Wol [HIDN*HIDN];

__device__ __align__(128) __half g_qh [GH*Sq*Dh];       // [g][s][d] scaled
__device__ __align__(128) __half g_kh [GH*Sq*Dh];       // [g][s][d]
__device__ __align__(128) __half g_vh [GH*Dh*Sq];       // [g][d][s] split
__device__ __align__(128) __half g_vl [GH*Dh*Sq];
__device__ __align__(128) __half g_xh [(long)GH*Sq*Sq]; // scores fp16
__device__ __align__(128) __half g_wTh[(long)Bsz*Sq*Sq];// w^T fp16
__device__ __align__(128) __half g_yh [(long)GH*Sq*Sq]; // logits fp16
__device__ __align__(128) __half g_ph [(long)GH*Sq*Sq]; // softmax split
__device__ __align__(128) __half g_pl [(long)GH*Sq*Sq];
__device__ __align__(128) __half g_oh [Bsz*Sq*HIDN];    // o split [b][s][hd]
__device__ __align__(128) __half g_ol [Bsz*Sq*HIDN];
__device__ int g_mask_mode;

// ---------------------------------------------------------------------------
// Mask dtype sniffer
// ---------------------------------------------------------------------------
__global__ void detect_mask_kernel(const unsigned int* __restrict__ m, int nwords) {
    __shared__ int s_multi;
    if (threadIdx.x == 0) s_multi = 0;
    __syncthreads();
    int found = 0;
    for (int i = threadIdx.x; i < nwords; i += blockDim.x) {
        unsigned int v = m[i];
        if (v > 1u && v != 0x3F800000u) found = 1;
    }
    if (found) atomicOr(&s_multi, 1);
    __syncthreads();
    if (threadIdx.x == 0) g_mask_mode = s_multi ? 2 : 0;
}
__device__ __forceinline__ bool mask_true(const void* mask, long idx) {
    if (g_mask_mode == 2) return ((const unsigned char*)mask)[idx] != 0;
    return ((const unsigned int*)mask)[idx] != 0u;
}

// ---------------------------------------------------------------------------
// Conversions (vectorized: float4 in, half2 out)
// ---------------------------------------------------------------------------
enum { C_Q = 0, C_K, C_WQ, C_WK };
enum { S_V = 0, S_WV, S_WO };

template <int WHICH>
__global__ void conv_half_t(const float* __restrict__ s, int n) {
    __half* d = (WHICH == C_Q)  ? g_q16 :
                (WHICH == C_K)  ? g_k16 :
                (WHICH == C_WQ) ? g_Wq16 : g_Wk16;
    int i = (blockIdx.x * blockDim.x + threadIdx.x) * 4;
    if (i < n) {
        float4 v = *(const float4*)(s + i);
        ((__half2*)(d + i))[0] = __floats2half2_rn(v.x, v.y);
        ((__half2*)(d + i))[1] = __floats2half2_rn(v.z, v.w);
    }
}

template <int WHICH>
__global__ void conv_split_t(const float* __restrict__ s, int n) {
    __half* h = (WHICH == S_V) ? g_v16h : (WHICH == S_WV) ? g_Wvh : g_Woh;
    __half* l = (WHICH == S_V) ? g_v16l : (WHICH == S_WV) ? g_Wvl : g_Wol;
    int i = (blockIdx.x * blockDim.x + threadIdx.x) * 4;
    if (i < n) {
        float4 v = *(const float4*)(s + i);
        float f[4] = {v.x, v.y, v.z, v.w};
        __half hh[4], ll[4];
        #pragma unroll
        for (int j = 0; j < 4; j++) {
            hh[j] = __float2half(f[j]);
            ll[j] = __float2half(f[j] - __half2float(hh[j]));
        }
        *(uint2*)(h + i) = *(uint2*)hh;
        *(uint2*)(l + i) = *(uint2*)ll;
    }
}

// w transpose -> fp16
__global__ void transpose_w_kernel(const float* __restrict__ w) {
    __shared__ float t[32][33];
    int b = blockIdx.z;
    int k0 = blockIdx.y * 32, l0 = blockIdx.x * 32;
    const float* wb = w + (long)b * Sq * Sq;
    __half* ob = g_wTh + (long)b * Sq * Sq;
    int x = threadIdx.x, y = threadIdx.y;
    #pragma unroll
    for (int i = 0; i < 32; i += 8)
        t[y + i][x] = wb[(long)(k0 + y + i) * Sq + (l0 + x)];
    __syncthreads();
    #pragma unroll
    for (int i = 0; i < 32; i += 8)
        ob[(long)(l0 + y + i) * Sq + (k0 + x)] = __float2half(t[x][y + i]);
}

// ---------------------------------------------------------------------------
// HMMA primitives
// ---------------------------------------------------------------------------
static __device__ __forceinline__ uint32_t sw64 (uint32_t x) { return x ^ ((x >> 3) & 0x30); }
static __device__ __forceinline__ uint32_t sw128(uint32_t x) { return x ^ ((x >> 3) & 0x70); }

__device__ __forceinline__ void cp_async16(uint32_t saddr, const void* gaddr) {
    asm volatile("cp.async.cg.shared.global [%0], [%1], 16;"
                 :: "r"(saddr), "l"(gaddr) : "memory");
}
__device__ __forceinline__ void ldsm_x4(uint32_t* r, uint32_t addr) {
    asm volatile("ldmatrix.sync.aligned.m8n8.x4.shared.b16 {%0,%1,%2,%3}, [%4];"
                 : "=r"(r[0]), "=r"(r[1]), "=r"(r[2]), "=r"(r[3]) : "r"(addr));
}
__device__ __forceinline__ void mma16816(float* c, const uint32_t* a, const uint32_t* b) {
    asm volatile(
        "mma.sync.aligned.m16n8k16.row.col.f32.f16.f16.f32 "
        "{%0,%1,%2,%3}, {%4,%5,%6,%7}, {%8,%9}, {%0,%1,%2,%3};"
        : "+f"(c[0]), "+f"(c[1]), "+f"(c[2]), "+f"(c[3])
        : "r"(a[0]), "r"(a[1]), "r"(a[2]), "r"(a[3]), "r"(b[0]), "r"(b[1]));
}
// fp16 accumulator variant (XW only): c = 2 regs = 4 packed halfs
__device__ __forceinline__ void mma16816_f16(uint32_t* c, const uint32_t* a, const uint32_t* b) {
    asm volatile(
        "mma.sync.aligned.m16n8k16.row.col.f16.f16.f16.f16 "
        "{%0,%1}, {%2,%3,%4,%5}, {%6,%7}, {%0,%1};"
        : "+r"(c[0]), "+r"(c[1])
        : "r"(a[0]), "r"(a[1]), "r"(a[2]), "r"(a[3]), "r"(b[0]), "r"(b[1]));
}

// ===========================================================================
// XW v4: y = x @ w^T per head, fp16 ACCUMULATOR (2x HMMA rate hypothesis).
// 128 threads (2x2 warps), BM=BN=128, warp tile 64x64, k-tile 64 (SW128),
// 3-stage dynamic-smem cp.async, register double-buffered fragments.
// Epilogue writes y fp16 directly.
// ===========================================================================
#define X2STAGE 32768                    // (128+128) rows * 128B
#define X2SMEM  (3*X2STAGE)              // 96 KB dynamic

__global__ void __launch_bounds__(128) xw4_kernel() {
    extern __shared__ __align__(1024) char smem2[];
    uint32_t sbase = (uint32_t)__cvta_generic_to_shared(smem2);

    int tid = threadIdx.x;
    int wid = tid >> 5, lane = tid & 31;
    int wm = (wid >> 1) * 64;
    int wn = (wid & 1) * 64;

    int g  = blockIdx.z;
    int m0 = blockIdx.y * 128;
    int n0 = blockIdx.x * 128;
    const __half* Ag = g_xh  + (long)g        * Sq * Sq + (long)m0 * Sq;
    const __half* Bg = g_wTh + (long)(g >> 3) * Sq * Sq + (long)n0 * Sq;

    uint32_t c[4][8][2];                 // packed half2 accumulators
    #pragma unroll
    for (int t = 0; t < 4; t++)
        #pragma unroll
        for (int u = 0; u < 8; u++) { c[t][u][0] = 0u; c[t][u][1] = 0u; }

    auto load_stage = [&](int st, int kt) {
        uint32_t base = sbase + st * X2STAGE;
        const __half* Ak = Ag + kt * 64;
        const __half* Bk = Bg + kt * 64;
        #pragma unroll
        for (int it = 0; it < 16; it++) {
            int t = tid + it * 128;            // 0..2047
            int r = t >> 3, ch = t & 7;
            if (r < 128)
                cp_async16(base + sw128(r * 128 + ch * 16),
                           Ak + (long)r * Sq + ch * 8);
            else {
                int rb = r - 128;
                cp_async16(base + 16384 + sw128(rb * 128 + ch * 16),
                           Bk + (long)rb * Sq + ch * 8);
            }
        }
    };

    load_stage(0, 0);
    asm volatile("cp.async.commit_group;" ::: "memory");
    load_stage(1, 1);
    asm volatile("cp.async.commit_group;" ::: "memory");

    uint32_t a[2][4][4], b[2][8][2];

    for (int kt = 0; kt < 32; kt++) {       // K=2048, tile 64
        int st = kt % 3;
        asm volatile("cp.async.wait_group 1;" ::: "memory");
        __syncthreads();

        int kn = kt + 2;
        if (kn < 32) load_stage(kn % 3, kn);
        asm volatile("cp.async.commit_group;" ::: "memory");

        uint32_t abase = sbase + st * X2STAGE;
        uint32_t bbase = abase + 16384;

        auto load_a = [&](int buf, int ks) {
            #pragma unroll
            for (int t = 0; t < 4; t++) {
                int row = wm + t * 16 + (lane & 15);
                ldsm_x4(a[buf][t], abase + sw128(row * 128 + ks * 32 + (lane >> 4) * 16));
            }
        };
        auto load_b = [&](int buf, int ks) {
            #pragma unroll
            for (int u = 0; u < 8; u += 2) {
                int grp = lane >> 3;
                int row = wn + u * 8 + (grp >> 1) * 8 + (lane & 7);
                int kb  = (grp & 1) * 16;
                uint32_t rr[4];
                ldsm_x4(rr, bbase + sw128(row * 128 + ks * 32 + kb));
                b[buf][u][0] = rr[0];     b[buf][u][1] = rr[1];
                b[buf][u + 1][0] = rr[2]; b[buf][u + 1][1] = rr[3];
            }
        };

        load_a(0, 0);
        load_b(0, 0);
        #pragma unroll
        for (int ks = 0; ks < 4; ks++) {
            int cur = ks & 1, nxt = cur ^ 1;
            if (ks < 3) { load_a(nxt, ks + 1); load_b(nxt, ks + 1); }
            #pragma unroll
            for (int t = 0; t < 4; t++)
                #pragma unroll
                for (int u = 0; u < 8; u++)
                    mma16816_f16(c[t][u], a[cur][t], b[cur][u]);
        }
    }

    // epilogue -> g_yh fp16 (c[..][0] = row m cols n,n+1 ; c[..][1] = row m+8)
    __half* Cg = g_yh + (long)g * Sq * Sq;
    #pragma unroll
    for (int t = 0; t < 4; t++) {
        int m = m0 + wm + t * 16 + (lane >> 2);
        #pragma unroll
        for (int u = 0; u < 8; u++) {
            int n = n0 + wn + u * 8 + (lane & 3) * 2;
            *(uint32_t*)(Cg + (long)m * Sq + n)       = c[t][u][0];
            *(uint32_t*)(Cg + (long)(m + 8) * Sq + n) = c[t][u][1];
        }
    }
}

// ---------------------------------------------------------------------------
// Unified HMMA GEMM template (proj/scores/ogemm/out), fp32 accumulators.
// NT: C = sum_seg A B^T.  128 threads, 2x2 warps, 3-stage cp.async, SW64.
// ---------------------------------------------------------------------------
enum { M_QPROJ = 0, M_KPROJ, M_VPROJ, M_SCORES, M_OGEMM, M_OUT };

template <int BM, int BN, int MODE>
__global__ void __launch_bounds__(128)
hgemm(const float* __restrict__ bias, const float* __restrict__ attn_bias,
      const void* __restrict__ mask, float* __restrict__ Cext)
{
    constexpr int KD   = (MODE == M_SCORES) ? 64 :
                         (MODE == M_OGEMM) ? 2048 : 512;
    constexpr int NSEG = (MODE == M_VPROJ || MODE == M_OGEMM || MODE == M_OUT) ? 3 : 1;
    constexpr int TPS  = KD / 32;
    constexpr int TOT  = NSEG * TPS;
    constexpr int ROWS = BM + BN;
    constexpr int STAGE = ROWS * 64;
    constexpr int TMF = BM / 2 / 16;
    constexpr int TNF = BN / 2 / 8;

    __shared__ __align__(1024) char smem[3 * STAGE];
    uint32_t sbase = (uint32_t)__cvta_generic_to_shared(smem);

    int tid = threadIdx.x;
    int wid = tid >> 5, lane = tid & 31;
    int wm = (wid >> 1) * (BM / 2);
    int wn = (wid & 1) * (BN / 2);

    int g  = blockIdx.z;
    int m0 = blockIdx.y * BM;
    int n0 = blockIdx.x * BN;

    const __half *A0, *A1 = nullptr, *A2 = nullptr;
    const __half *B0, *B1 = nullptr, *B2 = nullptr;
    if (MODE == M_QPROJ)      { A0 = g_q16;  B0 = g_Wq16; }
    else if (MODE == M_KPROJ) { A0 = g_k16;  B0 = g_Wk16; }
    else if (MODE == M_VPROJ) { A0 = g_v16h; A1 = g_v16h; A2 = g_v16l;
                                B0 = g_Wvh;  B1 = g_Wvl;  B2 = g_Wvh; }
    else if (MODE == M_SCORES){ A0 = g_qh + (long)g * Sq * Dh;
                                B0 = g_kh + (long)g * Sq * Dh; }
    else if (MODE == M_OGEMM) { long ao = (long)g * Sq * Sq;
                                long bo = (long)g * Dh * Sq;
                                A0 = g_ph + ao; A1 = g_ph + ao; A2 = g_pl + ao;
                                B0 = g_vh + bo; B1 = g_vl + bo; B2 = g_vh + bo; }
    else                      { A0 = g_oh;  A1 = g_oh; A2 = g_ol;
                                B0 = g_Woh; B1 = g_Wol; B2 = g_Woh; }
    A0 += (long)m0 * KD; if (NSEG == 3) { A1 += (long)m0 * KD; A2 += (long)m0 * KD; }
    B0 += (long)n0 * KD; if (NSEG == 3) { B1 += (long)n0 * KD; B2 += (long)n0 * KD; }

    float c[TMF][TNF][4];
    #pragma unroll
    for (int t = 0; t < TMF; t++)
        #pragma unroll
        for (int u = 0; u < TNF; u++)
            #pragma unroll
            for (int i = 0; i < 4; i++) c[t][u][i] = 0.f;

    auto load_stage = [&](int st, int kt) {
        int seg = kt / TPS, kk = kt % TPS;
        const __half* Ak = (NSEG == 1 || seg == 0) ? A0 : (seg == 1) ? A1 : A2;
        const __half* Bk = (NSEG == 1 || seg == 0) ? B0 : (seg == 1) ? B1 : B2;
        Ak += kk * 32; Bk += kk * 32;
        uint32_t base = sbase + st * STAGE;
        #pragma unroll
        for (int t = tid; t < ROWS * 4; t += 128) {
            int r = t >> 2, ch = t & 3;
            if (r < BM)
                cp_async16(base + sw64(r * 64 + ch * 16),
                           Ak + (long)r * KD + ch * 8);
            else {
                int rb = r - BM;
                cp_async16(base + BM * 64 + sw64(rb * 64 + ch * 16),
                           Bk + (long)rb * KD + ch * 8);
            }
        }
    };

    load_stage(0, 0);
    asm volatile("cp.async.commit_group;" ::: "memory");
    if (TOT > 1) load_stage(1, 1);
    asm volatile("cp.async.commit_group;" ::: "memory");

    for (int kt = 0; kt < TOT; kt++) {
        int st = kt % 3;
        asm volatile("cp.async.wait_group 1;" ::: "memory");
        __syncthreads();

        int kn = kt + 2;
        if (kn < TOT) load_stage(kn % 3, kn);
        asm volatile("cp.async.commit_group;" ::: "memory");

        uint32_t abase = sbase + st * STAGE;
        uint32_t bbase = abase + BM * 64;
        #pragma unroll
        for (int ks = 0; ks < 2; ks++) {
            uint32_t a[TMF][4], b[TNF][2];
            #pragma unroll
            for (int t = 0; t < TMF; t++) {
                int row = wm + t * 16 + (lane & 15);
                ldsm_x4(a[t], abase + sw64(row * 64 + ks * 32 + (lane >> 4) * 16));
            }
            #pragma unroll
            for (int u = 0; u < TNF; u += 2) {
                int grp = lane >> 3;
                int row = wn + u * 8 + (grp >> 1) * 8 + (lane & 7);
                int kb  = (grp & 1) * 16;
                uint32_t rr[4];
                ldsm_x4(rr, bbase + sw64(row * 64 + ks * 32 + kb));
                b[u][0] = rr[0]; b[u][1] = rr[1];
                b[u + 1][0] = rr[2]; b[u + 1][1] = rr[3];
            }
            #pragma unroll
            for (int t = 0; t < TMF; t++)
                #pragma unroll
                for (int u = 0; u < TNF; u++)
                    mma16816(c[t][u], a[t], b[u]);
        }
    }

    auto store = [&](int m, int n, float v) {
        if (MODE == M_QPROJ) {
            float val = (v + bias[n]) * 0.125f;
            int b_ = m >> 11, s = m & 2047, h = n >> 6, d = n & 63;
            g_qh[((long)((b_ * NHh + h) * Sq + s)) * Dh + d] = __float2half(val);
        } else if (MODE == M_KPROJ) {
            float val = v + bias[n];
            int b_ = m >> 11, s = m & 2047, h = n >> 6, d = n & 63;
            g_kh[((long)((b_ * NHh + h) * Sq + s)) * Dh + d] = __float2half(val);
        } else if (MODE == M_VPROJ) {
            float val = v + bias[n];
            int b_ = m >> 11, s = m & 2047, h = n >> 6, d = n & 63;
            long idx = ((long)((b_ * NHh + h) * Dh + d)) * Sq + s;
            __half hh = __float2half(val);
            g_vh[idx] = hh;
            g_vl[idx] = __float2half(val - __half2float(hh));
        } else if (MODE == M_SCORES) {
            long idx  = (long)g * Sq * Sq + (long)m * Sq + n;
            long midx = (long)(g >> 3) * Sq * Sq + (long)m * Sq + n;
            float val = v + attn_bias[idx];
            if (mask_true(mask, midx)) val = 0.f;
            g_xh[idx] = __float2half(val);
        } else if (MODE == M_OGEMM) {
            int b_ = g >> 3, h = g & 7;
            long idx = ((long)(b_ * Sq + m)) * HIDN + h * Dh + n;
            __half hh = __float2half(v);
            g_oh[idx] = hh;
            g_ol[idx] = __float2half(v - __half2float(hh));
        } else {  // M_OUT
            Cext[(long)m * HIDN + n] = v + bias[n];
        }
    };

    #pragma unroll
    for (int t = 0; t < TMF; t++) {
        int m = m0 + wm + t * 16 + (lane >> 2);
        #pragma unroll
        for (int u = 0; u < TNF; u++) {
            int n = n0 + wn + u * 8 + (lane & 3) * 2;
            store(m,     n,     c[t][u][0]);
            store(m,     n + 1, c[t][u][1]);
            store(m + 8, n,     c[t][u][2]);
            store(m + 8, n + 1, c[t][u][3]);
        }
    }
}

// ---------------------------------------------------------------------------
// Softmax v2: g_yh row (fp16) -> (ph, pl) fp16 split.  256 threads, 8 elems
// per thread register-resident, uint4 I/O, no smem row buffer.
// ---------------------------------------------------------------------------
__global__ void __launch_bounds__(256) softmax_kernel() {
    long row = blockIdx.x;
    const uint4* src = (const uint4*)(g_yh + row * Sq);
    __shared__ float red[256];
    int t = threadIdx.x;

    uint4 rv = src[t];                    // 8 halfs
    __half2 hp[4];
    *(uint4*)hp = rv;
    float v[8];
    #pragma unroll
    for (int j = 0; j < 4; j++) {
        float2 f = __half22float2(hp[j]);
        v[2 * j] = f.x; v[2 * j + 1] = f.y;
    }

    float mx = v[0];
    #pragma unroll
    for (int j = 1; j < 8; j++) mx = fmaxf(mx, v[j]);
    red[t] = mx; __syncthreads();
    for (int s = 128; s > 0; s >>= 1) {
        if (t < s) red[t] = fmaxf(red[t], red[t + s]);
        __syncthreads();
    }
    mx = red[0];
    __syncthreads();

    float e[8], sum = 0.f;
    #pragma unroll
    for (int j = 0; j < 8; j++) { e[j] = expf(v[j] - mx); sum += e[j]; }
    red[t] = sum; __syncthreads();
    for (int s = 128; s > 0; s >>= 1) {
        if (t < s) red[t] += red[t + s];
        __syncthreads();
    }
    float inv = 1.f / red[0];

    __half hh[8], ll[8];
    #pragma unroll
    for (int j = 0; j < 8; j++) {
        float pv = e[j] * inv;
        hh[j] = __float2half(pv);
        ll[j] = __float2half(pv - __half2float(hh[j]));
    }
    ((uint4*)(g_ph + row * Sq))[t] = *(uint4*)hh;
    ((uint4*)(g_pl + row * Sq))[t] = *(uint4*)ll;
}

// ---------------------------------------------------------------------------
extern "C" void kernel_launch(void* const* d_in, const int* in_sizes, int n_in,
                              void* d_out, int out_size)
{
    const float* q    = (const float*)d_in[0];
    const float* k    = (const float*)d_in[1];
    const float* v    = (const float*)d_in[2];
    const float* ab   = (const float*)d_in[3];
    const void*  mask = d_in[4];
    const float* w    = (const float*)d_in[5];
    const float* Wq   = (const float*)d_in[6];
    const float* bq   = (const float*)d_in[7];
    const float* Wk   = (const float*)d_in[8];
    const float* bk   = (const float*)d_in[9];
    const float* Wv   = (const float*)d_in[10];
    const float* bv   = (const float*)d_in[11];
    const float* Wo   = (const float*)d_in[12];
    const float* bo   = (const float*)d_in[13];
    float* out = (float*)d_out;

    const int NIN = Bsz * Sq * HIDN;      // 2M
    const int NW  = HIDN * HIDN;          // 256K

    cudaFuncSetAttribute(xw4_kernel,
                         cudaFuncAttributeMaxDynamicSharedMemorySize, X2SMEM);

    detect_mask_kernel<<<1, 256>>>((const unsigned int*)mask, 65536);

    conv_half_t<C_Q> <<<NIN / 4 / 512, 512>>>(q, NIN);
    conv_half_t<C_K> <<<NIN / 4 / 512, 512>>>(k, NIN);
    conv_split_t<S_V><<<NIN / 4 / 512, 512>>>(v, NIN);
    conv_half_t<C_WQ><<<NW / 4 / 128, 128>>>(Wq, NW);
    conv_half_t<C_WK><<<NW / 4 / 128, 128>>>(Wk, NW);
    conv_split_t<S_WV><<<NW / 4 / 128, 128>>>(Wv, NW);
    conv_split_t<S_WO><<<NW / 4 / 128, 128>>>(Wo, NW);

    transpose_w_kernel<<<dim3(64, 64, Bsz), dim3(32, 8)>>>(w);

    // Projections: [4096,512] @ [512,512]^T
    hgemm<128, 128, M_QPROJ><<<dim3(4, 32, 1), 128>>>(bq, nullptr, nullptr, nullptr);
    hgemm<128, 128, M_KPROJ><<<dim3(4, 32, 1), 128>>>(bk, nullptr, nullptr, nullptr);
    hgemm<128, 128, M_VPROJ><<<dim3(4, 32, 1), 128>>>(bv, nullptr, nullptr, nullptr);

    // Scores: [2048,64]@[2048,64]^T + bias, mask -> g_xh
    hgemm<128, 128, M_SCORES><<<dim3(16, 16, GH), 128>>>(nullptr, ab, mask, nullptr);

    // y = x @ w (dominant) — XW v4 (fp16 accumulators, fp16 y output)
    xw4_kernel<<<dim3(16, 16, GH), 128, X2SMEM>>>();

    softmax_kernel<<<GH * Sq, 256>>>();

    // o = p @ v^T  (split 3-pass): [2048,2048]@[64,2048]^T
    hgemm<128, 64, M_OGEMM><<<dim3(1, 16, GH), 128>>>(nullptr, nullptr, nullptr, nullptr);

    // out = o @ Wo^T + bo (split 3-pass)
    hgemm<128, 128, M_OUT><<<dim3(4, 32, 1), 128>>>(bo, nullptr, nullptr, out);
}